// round 8
// baseline (speedup 1.0000x reference)
#include <cuda_runtime.h>
#include <cstdint>

// Problem constants
#define CDIM  64
#define HW    4096            // 64*64
#define NROWS 65536           // B*H*W
#define KCODES 512
#define ROWPAD 68             // padded smem row stride (floats)
#define LOSS_OFS  4194304
#define PERP_OFS  4194305
#define ACT_OFS   4194306
#define IDX_OFS   4194307

#define MAIN_BLOCKS 128
#define MAIN_THREADS 512
// each block: 512 rows (1 per thread); 16 warps -> 4 per SMSP

__device__ int          g_hist[KCODES];      // zero at load; re-zeroed by last block
__device__ float        g_partial[MAIN_BLOCKS];
__device__ unsigned int g_done;              // zero at load; reset by last block

typedef unsigned long long ull;

__device__ __forceinline__ ull pack2(float lo, float hi) {
    ull r; asm("mov.b64 %0, {%1, %2};" : "=l"(r) : "f"(lo), "f"(hi)); return r;
}
__device__ __forceinline__ void unpack2(ull v, float& lo, float& hi) {
    asm("mov.b64 {%0, %1}, %2;" : "=f"(lo), "=f"(hi) : "l"(v));
}
__device__ __forceinline__ ull fma2(ull a, ull b, ull c) {
    ull d; asm("fma.rn.f32x2 %0, %1, %2, %3;" : "=l"(d) : "l"(a), "l"(b), "l"(c)); return d;
}
__device__ __forceinline__ ull add2(ull a, ull b) {
    ull d; asm("add.rn.f32x2 %0, %1, %2;" : "=l"(d) : "l"(a), "l"(b)); return d;
}

// ---------------- single fused kernel ----------------
__global__ __launch_bounds__(MAIN_THREADS, 1)
void vq_fused(const float* __restrict__ x, const float* __restrict__ emb,
              const float* __restrict__ weight, float* __restrict__ d_out) {
    extern __shared__ float sm[];
    float* se    = sm;                       // [512][68] padded codebook
    float* sssq  = sm + KCODES * ROWPAD;     // [512]
    int*   shist = (int*)(sssq + KCODES);    // [512]
    float* sred  = (float*)(shist + KCODES); // [512]
    __shared__ unsigned int s_last;

    const int tid = threadIdx.x;

    // load codebook into padded smem (float4, coalesced) + zero local hist
    for (int i = tid; i < KCODES * (CDIM / 4); i += MAIN_THREADS) {
        int r = i >> 4, q = i & 15;
        ((float4*)(se + r * ROWPAD))[q] = ((const float4*)emb)[i];
    }
    for (int i = tid; i < KCODES; i += MAIN_THREADS) shist[i] = 0;
    __syncthreads();

    // per-block ssq via lane rotation (conflict-free reads), 1 code row per thread
    {
        const int r = tid;  // KCODES == MAIN_THREADS
        const float* row = se + r * ROWPAD;
        float s = 0.f;
        const int rot = tid & 31;
#pragma unroll
        for (int c = 0; c < CDIM; ++c) {
            float v = row[(c + rot) & (CDIM - 1)];
            s = fmaf(v, v, s);
        }
        sssq[r] = s;
    }
    __syncthreads();

    // one row per thread
    const int r0 = blockIdx.x * 512 + tid;
    const int b0 = r0 >> 12, hw0 = r0 & 4095;
    const float* p0 = x + ((long)b0 << 18) + hw0;   // b*64*4096

    ull X[32];
#pragma unroll
    for (int j = 0; j < 32; ++j)
        X[j] = pack2(p0[(2 * j) * HW], p0[(2 * j + 1) * HW]);

    float best = 3.4e38f;
    int bi = 0;

    for (int k = 0; k < KCODES; ++k) {
        const ulonglong2* ep = (const ulonglong2*)(se + k * ROWPAD);
        ull a0 = 0, a1 = 0, a2 = 0, a3 = 0;
#pragma unroll
        for (int j = 0; j < 16; ++j) {
            ulonglong2 e = ep[j];
            if (j & 1) {
                a2 = fma2(X[2 * j],     e.x, a2);
                a3 = fma2(X[2 * j + 1], e.y, a3);
            } else {
                a0 = fma2(X[2 * j],     e.x, a0);
                a1 = fma2(X[2 * j + 1], e.y, a1);
            }
        }
        a0 = add2(add2(a0, a1), add2(a2, a3));
        float lo, hi;
        unpack2(a0, lo, hi);
        const float s = fmaf(-2.f, lo + hi, sssq[k]);
        if (s < best) { best = s; bi = k; }
    }

    // epilogue: gather code, write quantized output, commitment, histogram, index
    float csum = 0.f;
    {
        float* op = d_out + ((long)b0 << 18) + hw0;
        const float* er = se + bi * ROWPAD;
#pragma unroll
        for (int j = 0; j < 32; ++j) {
            float xl, xh;
            unpack2(X[j], xl, xh);
            float e0 = er[2 * j], e1 = er[2 * j + 1];
            float d0 = xl - e0, d1 = xh - e1;
            csum += d0 * d0 + d1 * d1;
            op[(2 * j) * HW]     = e0;
            op[(2 * j + 1) * HW] = e1;
        }
        d_out[IDX_OFS + r0] = (float)bi;
        atomicAdd(&shist[bi], 1);
    }

    // deterministic block reduction of commitment partial (512-wide tree)
    sred[tid] = csum;
    __syncthreads();
#pragma unroll
    for (int s = 256; s > 0; s >>= 1) {
        if (tid < s) sred[tid] += sred[tid + s];
        __syncthreads();
    }
    if (tid == 0) g_partial[blockIdx.x] = sred[0];

    // merge histogram into global
    {
        int c = shist[tid];
        if (c) atomicAdd(&g_hist[tid], c);
    }

    // ---- last-block finalize (fused, deterministic) ----
    __threadfence();
    __syncthreads();
    if (tid == 0) {
        unsigned int v = atomicAdd(&g_done, 1u);
        s_last = (v == MAIN_BLOCKS - 1) ? 1u : 0u;
    }
    __syncthreads();
    if (s_last) {
        __threadfence();  // acquire all blocks' g_partial / g_hist writes
        int   h = g_hist[tid];
        float q = (float)h * (1.f / (float)NROWS);
        float plog = q * logf(q + 1e-10f);
        int   act  = (weight[tid] >= 0.01f) ? 1 : 0;
        g_hist[tid] = 0;   // reset for next graph replay
        sred[tid]  = plog;
        shist[tid] = act;
        __syncthreads();
#pragma unroll
        for (int s = 256; s > 0; s >>= 1) {
            if (tid < s) { sred[tid] += sred[tid + s]; shist[tid] += shist[tid + s]; }
            __syncthreads();
        }
        if (tid == 0) {
            float s = 0.f;
            for (int i = 0; i < MAIN_BLOCKS; ++i) s += g_partial[i];  // fixed order
            d_out[LOSS_OFS] = s * (1.f / ((float)NROWS * (float)CDIM));
            d_out[PERP_OFS] = expf(-sred[0]);
            d_out[ACT_OFS]  = (float)shist[0];
            g_done = 0;  // reset for next replay
        }
    }
}

extern "C" void kernel_launch(void* const* d_in, const int* in_sizes, int n_in,
                              void* d_out, int out_size) {
    const float* x      = (const float*)d_in[0];  // [B,C,H,W]
    const float* emb    = (const float*)d_in[1];  // [K,C]
    const float* weight = (const float*)d_in[2];  // [K]
    float* out = (float*)d_out;

    static bool attr_set = false;
    const int smem = (KCODES * ROWPAD + KCODES + KCODES + MAIN_THREADS) * 4;
    if (!attr_set) {
        cudaFuncSetAttribute(vq_fused, cudaFuncAttributeMaxDynamicSharedMemorySize, smem);
        attr_set = true;
    }

    vq_fused<<<MAIN_BLOCKS, MAIN_THREADS, smem>>>(x, emb, weight, out);
}

// round 9
// speedup vs baseline: 1.2491x; 1.2491x over previous
#include <cuda_runtime.h>
#include <cstdint>

// Problem constants
#define CDIM  64
#define HW    4096            // 64*64
#define NROWS 65536           // B*H*W
#define KCODES 512
#define ROWPAD 68             // padded smem row stride (floats)
#define LOSS_OFS  4194304
#define PERP_OFS  4194305
#define ACT_OFS   4194306
#define IDX_OFS   4194307

#define MAIN_BLOCKS 128
#define MAIN_THREADS 256
// each block: 512 rows (2 per thread); 8 warps -> 2 per SMSP

__device__ int          g_hist[KCODES];      // zero at load; re-zeroed by last block
__device__ float        g_partial[MAIN_BLOCKS];
__device__ unsigned int g_done;              // zero at load; reset by last block

typedef unsigned long long ull;

__device__ __forceinline__ ull pack2(float lo, float hi) {
    ull r; asm("mov.b64 %0, {%1, %2};" : "=l"(r) : "f"(lo), "f"(hi)); return r;
}
__device__ __forceinline__ void unpack2(ull v, float& lo, float& hi) {
    asm("mov.b64 {%0, %1}, %2;" : "=f"(lo), "=f"(hi) : "l"(v));
}
__device__ __forceinline__ ull fma2(ull a, ull b, ull c) {
    ull d; asm("fma.rn.f32x2 %0, %1, %2, %3;" : "=l"(d) : "l"(a), "l"(b), "l"(c)); return d;
}
__device__ __forceinline__ ull add2(ull a, ull b) {
    ull d; asm("add.rn.f32x2 %0, %1, %2;" : "=l"(d) : "l"(a), "l"(b)); return d;
}

// ---------------- single fused kernel ----------------
__global__ __launch_bounds__(MAIN_THREADS, 1)
void vq_fused(const float* __restrict__ x, const float* __restrict__ emb,
              const float* __restrict__ weight, float* __restrict__ d_out) {
    extern __shared__ float sm[];
    float* se    = sm;                       // [512][68] padded codebook
    float* sssq  = sm + KCODES * ROWPAD;     // [512]
    int*   shist = (int*)(sssq + KCODES);    // [512]
    float* sred  = (float*)(shist + KCODES); // [256]
    __shared__ unsigned int s_last;

    const int tid = threadIdx.x;

    // load codebook into padded smem (float4, coalesced) + zero local hist
    for (int i = tid; i < KCODES * (CDIM / 4); i += MAIN_THREADS) {
        int r = i >> 4, q = i & 15;
        ((float4*)(se + r * ROWPAD))[q] = ((const float4*)emb)[i];
    }
    for (int i = tid; i < KCODES; i += MAIN_THREADS) shist[i] = 0;
    __syncthreads();

    // per-block ssq via lane rotation (conflict-free reads)
    for (int r = tid; r < KCODES; r += MAIN_THREADS) {
        const float* row = se + r * ROWPAD;
        float s = 0.f;
        const int rot = tid & 31;
#pragma unroll
        for (int c = 0; c < CDIM; ++c) {
            float v = row[(c + rot) & (CDIM - 1)];
            s = fmaf(v, v, s);
        }
        sssq[r] = s;
    }
    __syncthreads();

    // two rows per thread
    const int r0 = blockIdx.x * 512 + tid;
    const int r1 = r0 + 256;
    const int b0 = r0 >> 12, hw0 = r0 & 4095;
    const int b1 = r1 >> 12, hw1 = r1 & 4095;
    const float* p0 = x + ((long)b0 << 18) + hw0;   // b*64*4096
    const float* p1 = x + ((long)b1 << 18) + hw1;

    ull Xa[32], Xb[32];
#pragma unroll
    for (int j = 0; j < 32; ++j) {
        Xa[j] = pack2(p0[(2 * j) * HW], p0[(2 * j + 1) * HW]);
        Xb[j] = pack2(p1[(2 * j) * HW], p1[(2 * j + 1) * HW]);
    }

    float bestA = 3.4e38f, bestB = 3.4e38f;
    int biA = 0, biB = 0;

    // 2-k interleave: 8 independent FMA chains; k+1's LDS overlaps k's FMA;
    // per-k serial tails merge. unroll 2 -> 4-deep pipeline visible to ptxas.
#pragma unroll 2
    for (int k = 0; k < KCODES; k += 2) {
        const ulonglong2* ep0 = (const ulonglong2*)(se + k * ROWPAD);
        const ulonglong2* ep1 = (const ulonglong2*)(se + (k + 1) * ROWPAD);
        ull a0 = 0, a1 = 0, c0 = 0, c1 = 0;   // code k   : rows A, B
        ull d0 = 0, d1 = 0, f0 = 0, f1 = 0;   // code k+1 : rows A, B
#pragma unroll
        for (int j = 0; j < 16; ++j) {
            ulonglong2 e0 = ep0[j];
            ulonglong2 e1 = ep1[j];
            a0 = fma2(Xa[2 * j],     e0.x, a0);
            a1 = fma2(Xa[2 * j + 1], e0.y, a1);
            c0 = fma2(Xb[2 * j],     e0.x, c0);
            c1 = fma2(Xb[2 * j + 1], e0.y, c1);
            d0 = fma2(Xa[2 * j],     e1.x, d0);
            d1 = fma2(Xa[2 * j + 1], e1.y, d1);
            f0 = fma2(Xb[2 * j],     e1.x, f0);
            f1 = fma2(Xb[2 * j + 1], e1.y, f1);
        }
        a0 = add2(a0, a1);
        c0 = add2(c0, c1);
        d0 = add2(d0, d1);
        f0 = add2(f0, f1);
        float v0, v1, w0, w1;
        const float sq0 = sssq[k], sq1 = sssq[k + 1];
        unpack2(a0, v0, v1);
        const float sA0 = fmaf(-2.f, v0 + v1, sq0);
        unpack2(c0, w0, w1);
        const float sB0 = fmaf(-2.f, w0 + w1, sq0);
        unpack2(d0, v0, v1);
        const float sA1 = fmaf(-2.f, v0 + v1, sq1);
        unpack2(f0, w0, w1);
        const float sB1 = fmaf(-2.f, w0 + w1, sq1);
        if (sA0 < bestA) { bestA = sA0; biA = k; }
        if (sA1 < bestA) { bestA = sA1; biA = k + 1; }
        if (sB0 < bestB) { bestB = sB0; biB = k; }
        if (sB1 < bestB) { bestB = sB1; biB = k + 1; }
    }

    // epilogue: gather codes, write quantized output, commitment, histogram, indices
    float csum = 0.f;
    {
        float* op = d_out + ((long)b0 << 18) + hw0;
        const float* er = se + biA * ROWPAD;
#pragma unroll
        for (int j = 0; j < 32; ++j) {
            float xl, xh;
            unpack2(Xa[j], xl, xh);
            float e0 = er[2 * j], e1 = er[2 * j + 1];
            float dd0 = xl - e0, dd1 = xh - e1;
            csum += dd0 * dd0 + dd1 * dd1;
            op[(2 * j) * HW]     = e0;
            op[(2 * j + 1) * HW] = e1;
        }
        d_out[IDX_OFS + r0] = (float)biA;
        atomicAdd(&shist[biA], 1);
    }
    {
        float* op = d_out + ((long)b1 << 18) + hw1;
        const float* er = se + biB * ROWPAD;
#pragma unroll
        for (int j = 0; j < 32; ++j) {
            float xl, xh;
            unpack2(Xb[j], xl, xh);
            float e0 = er[2 * j], e1 = er[2 * j + 1];
            float dd0 = xl - e0, dd1 = xh - e1;
            csum += dd0 * dd0 + dd1 * dd1;
            op[(2 * j) * HW]     = e0;
            op[(2 * j + 1) * HW] = e1;
        }
        d_out[IDX_OFS + r1] = (float)biB;
        atomicAdd(&shist[biB], 1);
    }

    // deterministic block reduction of commitment partial
    sred[tid] = csum;
    __syncthreads();
#pragma unroll
    for (int s = 128; s > 0; s >>= 1) {
        if (tid < s) sred[tid] += sred[tid + s];
        __syncthreads();
    }
    if (tid == 0) g_partial[blockIdx.x] = sred[0];

    // merge histogram into global
    for (int i = tid; i < KCODES; i += MAIN_THREADS) {
        int c = shist[i];
        if (c) atomicAdd(&g_hist[i], c);
    }

    // ---- last-block finalize (fused, deterministic) ----
    __threadfence();
    __syncthreads();
    if (tid == 0) {
        unsigned int v = atomicAdd(&g_done, 1u);
        s_last = (v == MAIN_BLOCKS - 1) ? 1u : 0u;
    }
    __syncthreads();
    if (s_last) {
        __threadfence();  // acquire all blocks' g_partial / g_hist writes
        int   h0 = g_hist[tid], h1 = g_hist[tid + 256];
        float q0 = (float)h0 * (1.f / (float)NROWS);
        float q1 = (float)h1 * (1.f / (float)NROWS);
        float plog = q0 * logf(q0 + 1e-10f) + q1 * logf(q1 + 1e-10f);
        int   act  = (weight[tid] >= 0.01f ? 1 : 0) + (weight[tid + 256] >= 0.01f ? 1 : 0);
        g_hist[tid]       = 0;   // reset for next graph replay
        g_hist[tid + 256] = 0;
        sred[tid]  = plog;
        shist[tid] = act;
        __syncthreads();
#pragma unroll
        for (int s = 128; s > 0; s >>= 1) {
            if (tid < s) { sred[tid] += sred[tid + s]; shist[tid] += shist[tid + s]; }
            __syncthreads();
        }
        if (tid == 0) {
            float s = 0.f;
            for (int i = 0; i < MAIN_BLOCKS; ++i) s += g_partial[i];  // fixed order
            d_out[LOSS_OFS] = s * (1.f / ((float)NROWS * (float)CDIM));
            d_out[PERP_OFS] = expf(-sred[0]);
            d_out[ACT_OFS]  = (float)shist[0];
            g_done = 0;  // reset for next replay
        }
    }
}

extern "C" void kernel_launch(void* const* d_in, const int* in_sizes, int n_in,
                              void* d_out, int out_size) {
    const float* x      = (const float*)d_in[0];  // [B,C,H,W]
    const float* emb    = (const float*)d_in[1];  // [K,C]
    const float* weight = (const float*)d_in[2];  // [K]
    float* out = (float*)d_out;

    static bool attr_set = false;
    const int smem = (KCODES * ROWPAD + KCODES + KCODES + MAIN_THREADS) * 4;
    if (!attr_set) {
        cudaFuncSetAttribute(vq_fused, cudaFuncAttributeMaxDynamicSharedMemorySize, smem);
        attr_set = true;
    }

    vq_fused<<<MAIN_BLOCKS, MAIN_THREADS, smem>>>(x, emb, weight, out);
}